// round 11
// baseline (speedup 1.0000x reference)
#include <cuda_runtime.h>
#include <cuda_fp16.h>
#include <cstdint>

#define NROWS 8192
#define DIM   256
#define NTI   64                  // n-tiles (128 rows each)
#define MTI   64                  // m-tiles (128 rows each)
#define UNITS (NTI * MTI)         // 4096
#define GRID  296                 // 2 CTAs per SM
#define NSTAGE 3

// ---------------- device scratch (no allocation allowed) -------------------
__device__ __half g_Xhi[NROWS * DIM];
__device__ __half g_Yhi[NROWS * DIM];
__device__ float g_minM[NROWS];
__device__ float g_cex [NROWS];
__device__ int   g_done;

#define INVS 3.33333333333333f
#define LOGC 0.28503427112126587f      /* -log(0.3) - 0.5*log(2*pi) */

// SMEM per CTA: A (X hi) 4 kc-tiles [128r][64k] SW128 = 64KB; B 3 stages x 16KB
#define SM_A 0
#define SM_B (4 * 16384)
#define SMEM_TOTAL (SM_B + NSTAGE * 16384)   /* 114688 = 112KB -> 2 CTAs/SM */

// ---------------- helpers --------------------------------------------------
__device__ __forceinline__ uint32_t smem_u32(const void* p) {
    uint32_t a;
    asm("{ .reg .u64 t; cvta.to.shared.u64 t, %1; cvt.u32.u64 %0, t; }" : "=r"(a) : "l"(p));
    return a;
}
__device__ __forceinline__ uint64_t gmem_u64(const void* p) {
    uint64_t a;
    asm("cvta.to.global.u64 %0, %1;" : "=l"(a) : "l"(p));
    return a;
}
#define SWZ128(x) ((x) ^ (((x) >> 3) & 0x70))

#define CPASYNC16(dst, src) \
    asm volatile("cp.async.cg.shared.global [%0], [%1], 16;" :: "r"(dst), "l"(src) : "memory")
#define CP_COMMIT()  asm volatile("cp.async.commit_group;" ::: "memory")
#define CP_WAIT(n)   asm volatile("cp.async.wait_group %0;" :: "n"(n) : "memory")

__device__ __forceinline__ void ldsm_x4(uint32_t r[4], uint32_t addr) {
    asm volatile("ldmatrix.sync.aligned.m8n8.x4.shared.b16 {%0,%1,%2,%3}, [%4];"
                 : "=r"(r[0]), "=r"(r[1]), "=r"(r[2]), "=r"(r[3]) : "r"(addr));
}
__device__ __forceinline__ void mma16816(float c[4], const uint32_t a[4], const uint32_t b[2]) {
    asm("mma.sync.aligned.m16n8k16.row.col.f32.f16.f16.f32 "
        "{%0,%1,%2,%3}, {%4,%5,%6,%7}, {%8,%9}, {%0,%1,%2,%3};"
        : "+f"(c[0]), "+f"(c[1]), "+f"(c[2]), "+f"(c[3])
        : "r"(a[0]), "r"(a[1]), "r"(a[2]), "r"(a[3]), "r"(b[0]), "r"(b[1]));
}
// sign-aware atomic float min (target initialized to +INF)
__device__ __forceinline__ void atomicMinF(float* a, float v) {
    if (v >= 0.0f) atomicMin((int*)a, __float_as_int(v));
    else           atomicMax((unsigned int*)a, __float_as_uint(v));
}

// ---------------- normalize -> fp16 (warp per row) + state reset -----------
__global__ void __launch_bounds__(256) norm_kernel(const float* __restrict__ in, int which) {
    const int w = (blockIdx.x << 3) + (threadIdx.x >> 5);
    const int lane = threadIdx.x & 31;
    if (which == 0 && lane == 0) {               // graph-replay-safe resets
        g_minM[w] = __int_as_float(0x7f800000);
        g_cex [w] = __int_as_float(0x7f800000);
        if (w == 0) g_done = 0;
    }
    const float4* src = (const float4*)(in + w * DIM) + lane * 2;
    float4 v0 = src[0], v1 = src[1];
    float ss = v0.x*v0.x + v0.y*v0.y + v0.z*v0.z + v0.w*v0.w
             + v1.x*v1.x + v1.y*v1.y + v1.z*v1.z + v1.w*v1.w;
    #pragma unroll
    for (int o = 16; o; o >>= 1) ss += __shfl_xor_sync(0xFFFFFFFFu, ss, o);
    const float sc = 1.0f / fmaxf(sqrtf(ss), 1e-8f);
    __half2 hp[4];
    hp[0] = __floats2half2_rn(v0.x*sc, v0.y*sc);
    hp[1] = __floats2half2_rn(v0.z*sc, v0.w*sc);
    hp[2] = __floats2half2_rn(v1.x*sc, v1.y*sc);
    hp[3] = __floats2half2_rn(v1.z*sc, v1.w*sc);
    __half* dst = which ? g_Yhi : g_Xhi;
    *(uint4*)(dst + w * DIM + lane * 8) = *(uint4*)hp;
}

// ---------------- persistent HMMA GEMM + running-min + fused combine -------
// 256 threads: 8 warps as 4(I=n) x 2(J=m); warp tile 32n x 64m. 2 CTAs/SM.
__global__ void __launch_bounds__(256, 2) gemm_min_kernel(float* __restrict__ out) {
    extern __shared__ char smem[];
    const uint32_t sb = smem_u32(smem);
    const int tid = threadIdx.x, lane = tid & 31, wid = tid >> 5;
    const int warp_i = wid & 3;        // n-dim group (32 rows each)
    const int warp_j = wid >> 2;       // m-dim group (64 cols each)
    const float INF = __int_as_float(0x7f800000);

    const int bid = blockIdx.x;
    const int u0 = (int)(((long long)bid * UNITS) / GRID);
    const int u1 = (int)(((long long)(bid + 1) * UNITS) / GRID);
    const int c0 = u0 * 4, c1 = u1 * 4;
    int cur_nt = u0 >> 6;              // 64 units per n-tile

    const uint64_t xh = gmem_u64(g_Xhi), yh = gmem_u64(g_Yhi);

    auto load_A = [&](int nt) {
        int nBase = nt * 128;
        #pragma unroll 4
        for (int i = 0; i < 16; i++) {
            int idx = tid + 256 * i;
            int kc = idx >> 10, rem = idx & 1023;
            int row = rem >> 3, seg = rem & 7;
            uint64_t src = xh + 2ull * ((uint64_t)(nBase + row) * DIM + kc * 64 + seg * 8);
            uint32_t dst = sb + SM_A + kc * 16384 + SWZ128(row * 128 + seg * 16);
            CPASYNC16(dst, src);
        }
        CP_COMMIT(); CP_WAIT(0);
        __syncthreads();
    };

    auto issue_chunk = [&](int ci) {
        int s = ci % NSTAGE, mt = (ci >> 2) & 63, kc = ci & 3;
        int mBase = mt * 128;
        #pragma unroll
        for (int i = 0; i < 4; i++) {
            int idx = tid + 256 * i;
            int row = idx >> 3, seg = idx & 7;
            uint64_t src = yh + 2ull * ((uint64_t)(mBase + row) * DIM + kc * 64 + seg * 8);
            uint32_t dst = sb + SM_B + s * 16384 + SWZ128(row * 128 + seg * 16);
            CPASYNC16(dst, src);
        }
        CP_COMMIT();
    };

    // ---- per-thread ldmatrix address components ----
    const uint32_t xor7 = (lane & 7) << 4;
    const int aq = lane >> 3;
    const uint32_t a_k16 = (aq >> 1) << 4;
    const uint32_t b_k16 = ((lane >> 3) & 1) << 4;
    uint32_t rowA[2], rowB[4];
    #pragma unroll
    for (int mt = 0; mt < 2; mt++)
        rowA[mt] = (uint32_t)(warp_i * 32 + mt * 16 + ((aq & 1) << 3) + (lane & 7)) * 128;
    #pragma unroll
    for (int g = 0; g < 4; g++)
        rowB[g] = (uint32_t)(warp_j * 64 + g * 16 + (((lane >> 4) & 1) << 3) + (lane & 7)) * 128;

    float acc[2][8][4];
    #pragma unroll
    for (int mt = 0; mt < 2; mt++)
        #pragma unroll
        for (int nt = 0; nt < 8; nt++)
            #pragma unroll
            for (int e = 0; e < 4; e++) acc[mt][nt][e] = 0.0f;
    float rowmin[4], rowcex[4];
    #pragma unroll
    for (int i = 0; i < 4; i++) { rowmin[i] = INF; rowcex[i] = INF; }

    auto flush = [&](int nt) {
        __syncthreads();
        float* redM = (float*)smem;             // reuse A region: [128][8] x2
        float* redC = redM + 128 * 8;
        const int slot = warp_j * 4 + (lane & 3);
        #pragma unroll
        for (int i = 0; i < 4; i++) {
            int nl = warp_i * 32 + (i >> 1) * 16 + (i & 1) * 8 + (lane >> 2);
            redM[nl * 8 + slot] = rowmin[i];
            redC[nl * 8 + slot] = rowcex[i];
            rowmin[i] = INF; rowcex[i] = INF;
        }
        __syncthreads();
        if (tid < 128) {
            float m = INF, c = INF;
            #pragma unroll
            for (int k = 0; k < 8; k++) {
                m = fminf(m, redM[tid * 8 + k]);
                c = fminf(c, redC[tid * 8 + k]);
            }
            if (m < INF) atomicMinF(&g_minM[nt * 128 + tid], m);
            if (c < INF) atomicMinF(&g_cex [nt * 128 + tid], c);
        }
        __syncthreads();
    };

    load_A(cur_nt);
    issue_chunk(c0);
    if (c0 + 1 < c1) issue_chunk(c0 + 1);

    #pragma unroll 1
    for (int ci = c0; ci < c1; ci++) {
        if ((ci & 3) == 0) {
            int nt = ci >> 8;                    // (ci/4)/64
            if (nt != cur_nt) {
                flush(cur_nt);
                load_A(nt);                      // drains pending B copies (ok)
                cur_nt = nt;
            }
        }
        CP_WAIT(1);                              // chunk ci arrived
        __syncthreads();                         // all warps done reading ci-1
        if (ci + 2 < c1) issue_chunk(ci + 2);    // stage (ci+2)%3: safe post-sync

        const int s = ci % NSTAGE, kc = ci & 3;
        const uint32_t aHi = sb + SM_A + kc * 16384;
        const uint32_t bHi = sb + SM_B + s * 16384;

        // A fragments preloaded two ks-steps ahead (frees the ks loop to be
        // B-only, giving ptxas slack to hoist B ldsm into prior MMAs)
        uint32_t Aks[2][2][4];
        #pragma unroll
        for (int h = 0; h < 2; h++) {
            const uint32_t kbA = ((uint32_t)(h * 32) + a_k16) ^ xor7;
            ldsm_x4(Aks[h][0], aHi + rowA[0] + kbA);
            ldsm_x4(Aks[h][1], aHi + rowA[1] + kbA);
        }

        #pragma unroll
        for (int ks = 0; ks < 4; ks++) {
            if (ks == 2) {
                #pragma unroll
                for (int h = 0; h < 2; h++) {
                    const uint32_t kbA = ((uint32_t)((2 + h) * 32) + a_k16) ^ xor7;
                    ldsm_x4(Aks[h][0], aHi + rowA[0] + kbA);
                    ldsm_x4(Aks[h][1], aHi + rowA[1] + kbA);
                }
            }
            const int h = ks & 1;
            const uint32_t kbB = ((uint32_t)(ks * 32) + b_k16) ^ xor7;
            #pragma unroll
            for (int g = 0; g < 4; g++) {
                uint32_t r[4];
                ldsm_x4(r, bHi + rowB[g] + kbB);
                uint32_t b0[2] = {r[0], r[1]}, b1[2] = {r[2], r[3]};
                mma16816(acc[0][2*g],   Aks[h][0], b0);
                mma16816(acc[0][2*g+1], Aks[h][0], b1);
                mma16816(acc[1][2*g],   Aks[h][1], b0);
                mma16816(acc[1][2*g+1], Aks[h][1], b1);
            }
        }

        if ((ci & 3) == 3) {   // m-tile complete: fold into running row-mins
            #pragma unroll
            for (int mt = 0; mt < 2; mt++)
                #pragma unroll
                for (int nt = 0; nt < 8; nt++)
                    #pragma unroll
                    for (int e = 0; e < 4; e++) {
                        float M = acc[mt][nt][e];
                        acc[mt][nt][e] = 0.0f;
                        int ri = mt * 2 + (e >> 1);
                        if (M > 0.5f) {      // cold exact path (monotonicity edge)
                            float z = (M - 1.0f) * INVS;
                            float lp = fmaf(-0.5f * z, z, LOGC);
                            rowcex[ri] = fminf(rowcex[ri], -expf(lp) * lp);
                        } else {
                            rowmin[ri] = fminf(rowmin[ri], M);
                        }
                    }
        }
    }
    flush(cur_nt);

    // ---- fused combine: last CTA to finish writes the output --------------
    __shared__ int is_last;
    __threadfence();
    if (tid == 0) is_last = (atomicAdd(&g_done, 1) == GRID - 1);
    __syncthreads();
    if (is_last) {
        for (int n = tid; n < NROWS; n += 256) {
            float m  = __ldcg(&g_minM[n]);
            float ce = __ldcg(&g_cex[n]);
            float C = INF;
            if (m < 2.0f) {
                float z = (m - 1.0f) * INVS;
                float lp = fmaf(-0.5f * z, z, LOGC);
                C = -expf(lp) * lp;
            }
            out[n] = fminf(C, ce);
        }
    }
}

// ---------------------------------------------------------------------------
extern "C" void kernel_launch(void* const* d_in, const int* in_sizes, int n_in,
                              void* d_out, int out_size) {
    const float* Ex = (const float*)d_in[0];
    const float* Ey = (const float*)d_in[1];
    float* out = (float*)d_out;

    norm_kernel<<<NROWS / 8, 256>>>(Ex, 0);
    norm_kernel<<<NROWS / 8, 256>>>(Ey, 1);

    cudaFuncSetAttribute(gemm_min_kernel,
                         cudaFuncAttributeMaxDynamicSharedMemorySize, SMEM_TOTAL);
    gemm_min_kernel<<<GRID, 256, SMEM_TOTAL>>>(out);
}

// round 14
// speedup vs baseline: 1.0207x; 1.0207x over previous
#include <cuda_runtime.h>
#include <cuda_fp16.h>
#include <cstdint>

#define NROWS 8192
#define DIM   256
#define NTI   64                  // n-tiles (128 rows each)
#define MTI   64                  // m-tiles (128 rows each)
#define UNITS (NTI * MTI)         // 4096
#define GRID  296                 // 2 CTAs per SM
#define NSTAGE 3

// ---------------- device scratch (no allocation allowed) -------------------
__device__ __half g_Xhi[NROWS * DIM];
__device__ __half g_Yhi[NROWS * DIM];
__device__ float g_minM[NROWS];
__device__ float g_cex [NROWS];
__device__ int   g_done;

#define INVS 3.33333333333333f
#define LOGC 0.28503427112126587f      /* -log(0.3) - 0.5*log(2*pi) */

// SMEM per CTA: A (X hi) 4 kc-tiles [128r][64k] SW128 = 64KB; B 3 stages x 16KB
#define SM_A 0
#define SM_B (4 * 16384)
#define SMEM_TOTAL (SM_B + NSTAGE * 16384)   /* 114688 = 112KB -> 2 CTAs/SM */

// ---------------- helpers --------------------------------------------------
__device__ __forceinline__ uint32_t smem_u32(const void* p) {
    uint32_t a;
    asm("{ .reg .u64 t; cvta.to.shared.u64 t, %1; cvt.u32.u64 %0, t; }" : "=r"(a) : "l"(p));
    return a;
}
__device__ __forceinline__ uint64_t gmem_u64(const void* p) {
    uint64_t a;
    asm("cvta.to.global.u64 %0, %1;" : "=l"(a) : "l"(p));
    return a;
}
#define SWZ128(x) ((x) ^ (((x) >> 3) & 0x70))

#define CPASYNC16(dst, src) \
    asm volatile("cp.async.cg.shared.global [%0], [%1], 16;" :: "r"(dst), "l"(src) : "memory")
#define CP_COMMIT()  asm volatile("cp.async.commit_group;" ::: "memory")
#define CP_WAIT(n)   asm volatile("cp.async.wait_group %0;" :: "n"(n) : "memory")

__device__ __forceinline__ void ldsm_x4(uint32_t r[4], uint32_t addr) {
    asm volatile("ldmatrix.sync.aligned.m8n8.x4.shared.b16 {%0,%1,%2,%3}, [%4];"
                 : "=r"(r[0]), "=r"(r[1]), "=r"(r[2]), "=r"(r[3]) : "r"(addr));
}
__device__ __forceinline__ void mma16816(float c[4], const uint32_t a[4], const uint32_t b[2]) {
    asm("mma.sync.aligned.m16n8k16.row.col.f32.f16.f16.f32 "
        "{%0,%1,%2,%3}, {%4,%5,%6,%7}, {%8,%9}, {%0,%1,%2,%3};"
        : "+f"(c[0]), "+f"(c[1]), "+f"(c[2]), "+f"(c[3])
        : "r"(a[0]), "r"(a[1]), "r"(a[2]), "r"(a[3]), "r"(b[0]), "r"(b[1]));
}
// sign-aware atomic float min (target initialized to +INF)
__device__ __forceinline__ void atomicMinF(float* a, float v) {
    if (v >= 0.0f) atomicMin((int*)a, __float_as_int(v));
    else           atomicMax((unsigned int*)a, __float_as_uint(v));
}

// ---------------- normalize -> fp16 (2 rows per warp) + state reset --------
// grid: (NROWS/16, 2); grid.y = 0 -> Ex, 1 -> Ey
__global__ void __launch_bounds__(256) norm_kernel(const float* __restrict__ Ex,
                                                   const float* __restrict__ Ey) {
    const int which = blockIdx.y;
    const int w = (blockIdx.x << 4) + ((threadIdx.x >> 5) << 1);  // first of 2 rows
    const int lane = threadIdx.x & 31;
    const float* in = which ? Ey : Ex;
    if (which == 0 && lane < 2) {                // graph-replay-safe resets
        g_minM[w + lane] = __int_as_float(0x7f800000);
        g_cex [w + lane] = __int_as_float(0x7f800000);
        if (w == 0 && lane == 0) g_done = 0;
    }
    #pragma unroll
    for (int r = 0; r < 2; r++) {
        const int row = w + r;
        const float4* src = (const float4*)(in + row * DIM) + lane * 2;
        float4 v0 = src[0], v1 = src[1];
        float ss = v0.x*v0.x + v0.y*v0.y + v0.z*v0.z + v0.w*v0.w
                 + v1.x*v1.x + v1.y*v1.y + v1.z*v1.z + v1.w*v1.w;
        #pragma unroll
        for (int o = 16; o; o >>= 1) ss += __shfl_xor_sync(0xFFFFFFFFu, ss, o);
        const float sc = 1.0f / fmaxf(sqrtf(ss), 1e-8f);
        __half2 hp[4];
        hp[0] = __floats2half2_rn(v0.x*sc, v0.y*sc);
        hp[1] = __floats2half2_rn(v0.z*sc, v0.w*sc);
        hp[2] = __floats2half2_rn(v1.x*sc, v1.y*sc);
        hp[3] = __floats2half2_rn(v1.z*sc, v1.w*sc);
        __half* dst = which ? g_Yhi : g_Xhi;
        *(uint4*)(dst + row * DIM + lane * 8) = *(uint4*)hp;
    }
}

// ---------------- persistent HMMA GEMM + running-min + fused combine -------
// 256 threads: 8 warps as 4(I=n) x 2(J=m); warp tile 32n x 64m. 2 CTAs/SM.
__global__ void __launch_bounds__(256, 2) gemm_min_kernel(float* __restrict__ out) {
    extern __shared__ char smem[];
    const uint32_t sb = smem_u32(smem);
    const int tid = threadIdx.x, lane = tid & 31, wid = tid >> 5;
    const int warp_i = wid & 3;        // n-dim group (32 rows each)
    const int warp_j = wid >> 2;       // m-dim group (64 cols each)
    const float INF = __int_as_float(0x7f800000);

    const int bid = blockIdx.x;
    const int u0 = (int)(((long long)bid * UNITS) / GRID);
    const int u1 = (int)(((long long)(bid + 1) * UNITS) / GRID);
    const int c0 = u0 * 4, c1 = u1 * 4;
    int cur_nt = u0 >> 6;              // 64 units per n-tile

    const uint64_t xh = gmem_u64(g_Xhi), yh = gmem_u64(g_Yhi);

    auto load_A = [&](int nt) {
        int nBase = nt * 128;
        #pragma unroll 4
        for (int i = 0; i < 16; i++) {
            int idx = tid + 256 * i;
            int kc = idx >> 10, rem = idx & 1023;
            int row = rem >> 3, seg = rem & 7;
            uint64_t src = xh + 2ull * ((uint64_t)(nBase + row) * DIM + kc * 64 + seg * 8);
            uint32_t dst = sb + SM_A + kc * 16384 + SWZ128(row * 128 + seg * 16);
            CPASYNC16(dst, src);
        }
        CP_COMMIT(); CP_WAIT(0);
        __syncthreads();
    };

    auto issue_chunk = [&](int ci) {
        int s = ci % NSTAGE, mt = (ci >> 2) & 63, kc = ci & 3;
        int mBase = mt * 128;
        #pragma unroll
        for (int i = 0; i < 4; i++) {
            int idx = tid + 256 * i;
            int row = idx >> 3, seg = idx & 7;
            uint64_t src = yh + 2ull * ((uint64_t)(mBase + row) * DIM + kc * 64 + seg * 8);
            uint32_t dst = sb + SM_B + s * 16384 + SWZ128(row * 128 + seg * 16);
            CPASYNC16(dst, src);
        }
        CP_COMMIT();
    };

    // ---- per-thread ldmatrix address components ----
    const uint32_t xor7 = (lane & 7) << 4;
    const int aq = lane >> 3;
    const uint32_t a_k16 = (aq >> 1) << 4;
    const uint32_t b_k16 = ((lane >> 3) & 1) << 4;
    uint32_t rowA[2], rowB[4];
    #pragma unroll
    for (int mt = 0; mt < 2; mt++)
        rowA[mt] = (uint32_t)(warp_i * 32 + mt * 16 + ((aq & 1) << 3) + (lane & 7)) * 128;
    #pragma unroll
    for (int g = 0; g < 4; g++)
        rowB[g] = (uint32_t)(warp_j * 64 + g * 16 + (((lane >> 4) & 1) << 3) + (lane & 7)) * 128;

    float acc[2][8][4];
    #pragma unroll
    for (int mt = 0; mt < 2; mt++)
        #pragma unroll
        for (int nt = 0; nt < 8; nt++)
            #pragma unroll
            for (int e = 0; e < 4; e++) acc[mt][nt][e] = 0.0f;
    float rowmin[4], rowcex[4];
    #pragma unroll
    for (int i = 0; i < 4; i++) { rowmin[i] = INF; rowcex[i] = INF; }

    auto flush = [&](int nt) {
        __syncthreads();
        float* redM = (float*)smem;             // reuse A region: [128][8] x2
        float* redC = redM + 128 * 8;
        const int slot = warp_j * 4 + (lane & 3);
        #pragma unroll
        for (int i = 0; i < 4; i++) {
            int nl = warp_i * 32 + (i >> 1) * 16 + (i & 1) * 8 + (lane >> 2);
            redM[nl * 8 + slot] = rowmin[i];
            redC[nl * 8 + slot] = rowcex[i];
            rowmin[i] = INF; rowcex[i] = INF;
        }
        __syncthreads();
        if (tid < 128) {
            float m = INF, c = INF;
            #pragma unroll
            for (int k = 0; k < 8; k++) {
                m = fminf(m, redM[tid * 8 + k]);
                c = fminf(c, redC[tid * 8 + k]);
            }
            if (m < INF) atomicMinF(&g_minM[nt * 128 + tid], m);
            if (c < INF) atomicMinF(&g_cex [nt * 128 + tid], c);
        }
        __syncthreads();
    };

    load_A(cur_nt);
    issue_chunk(c0);
    if (c0 + 1 < c1) issue_chunk(c0 + 1);

    #pragma unroll 1
    for (int ci = c0; ci < c1; ci++) {
        if ((ci & 3) == 0) {
            int nt = ci >> 8;                    // (ci/4)/64
            if (nt != cur_nt) {
                flush(cur_nt);
                load_A(nt);                      // drains pending B copies (ok)
                cur_nt = nt;
            }
        }
        CP_WAIT(1);                              // chunk ci arrived
        __syncthreads();                         // all warps done reading ci-1
        if (ci + 2 < c1) issue_chunk(ci + 2);    // stage (ci+2)%3: safe post-sync

        const int s = ci % NSTAGE, kc = ci & 3;
        const uint32_t aHi = sb + SM_A + kc * 16384;
        const uint32_t bHi = sb + SM_B + s * 16384;

        #pragma unroll
        for (int ks = 0; ks < 4; ks++) {
            const uint32_t kbA = ((uint32_t)(ks * 32) + a_k16) ^ xor7;
            const uint32_t kbB = ((uint32_t)(ks * 32) + b_k16) ^ xor7;
            uint32_t Ah[2][4];
            #pragma unroll
            for (int mt = 0; mt < 2; mt++)
                ldsm_x4(Ah[mt], aHi + rowA[mt] + kbA);
            #pragma unroll
            for (int g = 0; g < 4; g++) {
                uint32_t r[4];
                ldsm_x4(r, bHi + rowB[g] + kbB);
                uint32_t b0[2] = {r[0], r[1]}, b1[2] = {r[2], r[3]};
                mma16816(acc[0][2*g],   Ah[0], b0);
                mma16816(acc[0][2*g+1], Ah[0], b1);
                mma16816(acc[1][2*g],   Ah[1], b0);
                mma16816(acc[1][2*g+1], Ah[1], b1);
            }
        }

        if ((ci & 3) == 3) {   // m-tile complete: fold into running row-mins
            #pragma unroll
            for (int mt = 0; mt < 2; mt++)
                #pragma unroll
                for (int nt = 0; nt < 8; nt++)
                    #pragma unroll
                    for (int e = 0; e < 4; e++) {
                        float M = acc[mt][nt][e];
                        acc[mt][nt][e] = 0.0f;
                        int ri = mt * 2 + (e >> 1);
                        if (M > 0.5f) {      // cold exact path (monotonicity edge)
                            float z = (M - 1.0f) * INVS;
                            float lp = fmaf(-0.5f * z, z, LOGC);
                            rowcex[ri] = fminf(rowcex[ri], -expf(lp) * lp);
                        } else {
                            rowmin[ri] = fminf(rowmin[ri], M);
                        }
                    }
        }
    }
    flush(cur_nt);

    // ---- fused combine: last CTA to finish writes the output --------------
    __shared__ int is_last;
    __threadfence();
    if (tid == 0) is_last = (atomicAdd(&g_done, 1) == GRID - 1);
    __syncthreads();
    if (is_last) {
        for (int n = tid; n < NROWS; n += 256) {
            float m  = __ldcg(&g_minM[n]);
            float ce = __ldcg(&g_cex[n]);
            float C = INF;
            if (m < 2.0f) {
                float z = (m - 1.0f) * INVS;
                float lp = fmaf(-0.5f * z, z, LOGC);
                C = -expf(lp) * lp;
            }
            out[n] = fminf(C, ce);
        }
    }
}

// ---------------------------------------------------------------------------
extern "C" void kernel_launch(void* const* d_in, const int* in_sizes, int n_in,
                              void* d_out, int out_size) {
    const float* Ex = (const float*)d_in[0];
    const float* Ey = (const float*)d_in[1];
    float* out = (float*)d_out;

    dim3 ngrid(NROWS / 16, 2);
    norm_kernel<<<ngrid, 256>>>(Ex, Ey);

    cudaFuncSetAttribute(gemm_min_kernel,
                         cudaFuncAttributeMaxDynamicSharedMemorySize, SMEM_TOTAL);
    gemm_min_kernel<<<GRID, 256, SMEM_TOTAL>>>(out);
}

// round 15
// speedup vs baseline: 1.2394x; 1.2142x over previous
#include <cuda_runtime.h>
#include <cuda_fp16.h>
#include <cstdint>

#define NROWS 8192
#define DIM   256
#define NTI   64                  // n-tiles (128 rows each)
#define MTI   64                  // m-tiles (128 rows each)
#define UNITS (NTI * MTI)         // 4096
#define GRID  296                 // 2 CTAs per SM
#define NSTAGE 3

// ---------------- device scratch (no allocation allowed) -------------------
__device__ __half g_Xhi[NROWS * DIM];
__device__ __half g_Yhi[NROWS * DIM];
__device__ float g_minM[NROWS];
__device__ float g_cex [NROWS];

#define INVS 3.33333333333333f
#define LOGC 0.28503427112126587f      /* -log(0.3) - 0.5*log(2*pi) */

// SMEM per CTA: A (X hi) 4 kc-tiles [128r][64k] SW128 = 64KB; B 3 stages x 16KB
#define SM_A 0
#define SM_B (4 * 16384)
#define SMEM_TOTAL (SM_B + NSTAGE * 16384)   /* 114688 = 112KB -> 2 CTAs/SM */

// ---------------- helpers --------------------------------------------------
__device__ __forceinline__ uint32_t smem_u32(const void* p) {
    uint32_t a;
    asm("{ .reg .u64 t; cvta.to.shared.u64 t, %1; cvt.u32.u64 %0, t; }" : "=r"(a) : "l"(p));
    return a;
}
__device__ __forceinline__ uint64_t gmem_u64(const void* p) {
    uint64_t a;
    asm("cvta.to.global.u64 %0, %1;" : "=l"(a) : "l"(p));
    return a;
}
#define SWZ128(x) ((x) ^ (((x) >> 3) & 0x70))

#define CPASYNC16(dst, src) \
    asm volatile("cp.async.cg.shared.global [%0], [%1], 16;" :: "r"(dst), "l"(src) : "memory")
#define CP_COMMIT()  asm volatile("cp.async.commit_group;" ::: "memory")
#define CP_WAIT(n)   asm volatile("cp.async.wait_group %0;" :: "n"(n) : "memory")

__device__ __forceinline__ void ldsm_x4(uint32_t r[4], uint32_t addr) {
    asm volatile("ldmatrix.sync.aligned.m8n8.x4.shared.b16 {%0,%1,%2,%3}, [%4];"
                 : "=r"(r[0]), "=r"(r[1]), "=r"(r[2]), "=r"(r[3]) : "r"(addr));
}
__device__ __forceinline__ void mma16816(float c[4], const uint32_t a[4], const uint32_t b[2]) {
    asm("mma.sync.aligned.m16n8k16.row.col.f32.f16.f16.f32 "
        "{%0,%1,%2,%3}, {%4,%5,%6,%7}, {%8,%9}, {%0,%1,%2,%3};"
        : "+f"(c[0]), "+f"(c[1]), "+f"(c[2]), "+f"(c[3])
        : "r"(a[0]), "r"(a[1]), "r"(a[2]), "r"(a[3]), "r"(b[0]), "r"(b[1]));
}
// sign-aware atomic float min (target initialized to +INF)
__device__ __forceinline__ void atomicMinF(float* a, float v) {
    if (v >= 0.0f) atomicMin((int*)a, __float_as_int(v));
    else           atomicMax((unsigned int*)a, __float_as_uint(v));
}

// ---------------- normalize -> fp16 (2 rows per warp) + state reset --------
// grid: (NROWS/16, 2); grid.y = 0 -> Ex, 1 -> Ey
__global__ void __launch_bounds__(256) norm_kernel(const float* __restrict__ Ex,
                                                   const float* __restrict__ Ey) {
    const int which = blockIdx.y;
    const int w = (blockIdx.x << 4) + ((threadIdx.x >> 5) << 1);  // first of 2 rows
    const int lane = threadIdx.x & 31;
    const float* in = which ? Ey : Ex;
    if (which == 0 && lane < 2) {                // graph-replay-safe resets
        g_minM[w + lane] = __int_as_float(0x7f800000);
        g_cex [w + lane] = __int_as_float(0x7f800000);
    }
    #pragma unroll
    for (int r = 0; r < 2; r++) {
        const int row = w + r;
        const float4* src = (const float4*)(in + row * DIM) + lane * 2;
        float4 v0 = src[0], v1 = src[1];
        float ss = v0.x*v0.x + v0.y*v0.y + v0.z*v0.z + v0.w*v0.w
                 + v1.x*v1.x + v1.y*v1.y + v1.z*v1.z + v1.w*v1.w;
        #pragma unroll
        for (int o = 16; o; o >>= 1) ss += __shfl_xor_sync(0xFFFFFFFFu, ss, o);
        const float sc = 1.0f / fmaxf(sqrtf(ss), 1e-8f);
        __half2 hp[4];
        hp[0] = __floats2half2_rn(v0.x*sc, v0.y*sc);
        hp[1] = __floats2half2_rn(v0.z*sc, v0.w*sc);
        hp[2] = __floats2half2_rn(v1.x*sc, v1.y*sc);
        hp[3] = __floats2half2_rn(v1.z*sc, v1.w*sc);
        __half* dst = which ? g_Yhi : g_Xhi;
        *(uint4*)(dst + row * DIM + lane * 8) = *(uint4*)hp;
    }
}

// ---------------- persistent HMMA GEMM + running-min -----------------------
// 256 threads: 8 warps as 4(I=n) x 2(J=m); warp tile 32n x 64m. 2 CTAs/SM.
__global__ void __launch_bounds__(256, 2) gemm_min_kernel() {
    extern __shared__ char smem[];
    const uint32_t sb = smem_u32(smem);
    const int tid = threadIdx.x, lane = tid & 31, wid = tid >> 5;
    const int warp_i = wid & 3;        // n-dim group (32 rows each)
    const int warp_j = wid >> 2;       // m-dim group (64 cols each)
    const float INF = __int_as_float(0x7f800000);

    const int bid = blockIdx.x;
    const int u0 = (int)(((long long)bid * UNITS) / GRID);
    const int u1 = (int)(((long long)(bid + 1) * UNITS) / GRID);
    const int c0 = u0 * 4, c1 = u1 * 4;
    int cur_nt = u0 >> 6;              // 64 units per n-tile

    const uint64_t xh = gmem_u64(g_Xhi), yh = gmem_u64(g_Yhi);

    auto load_A = [&](int nt) {
        int nBase = nt * 128;
        #pragma unroll 4
        for (int i = 0; i < 16; i++) {
            int idx = tid + 256 * i;
            int kc = idx >> 10, rem = idx & 1023;
            int row = rem >> 3, seg = rem & 7;
            uint64_t src = xh + 2ull * ((uint64_t)(nBase + row) * DIM + kc * 64 + seg * 8);
            uint32_t dst = sb + SM_A + kc * 16384 + SWZ128(row * 128 + seg * 16);
            CPASYNC16(dst, src);
        }
        CP_COMMIT(); CP_WAIT(0);
        __syncthreads();
    };

    auto issue_chunk = [&](int ci) {
        int s = ci % NSTAGE, mt = (ci >> 2) & 63, kc = ci & 3;
        int mBase = mt * 128;
        #pragma unroll
        for (int i = 0; i < 4; i++) {
            int idx = tid + 256 * i;
            int row = idx >> 3, seg = idx & 7;
            uint64_t src = yh + 2ull * ((uint64_t)(mBase + row) * DIM + kc * 64 + seg * 8);
            uint32_t dst = sb + SM_B + s * 16384 + SWZ128(row * 128 + seg * 16);
            CPASYNC16(dst, src);
        }
        CP_COMMIT();
    };

    // ---- per-thread ldmatrix address components ----
    const uint32_t xor7 = (lane & 7) << 4;
    const int aq = lane >> 3;
    const uint32_t a_k16 = (aq >> 1) << 4;
    const uint32_t b_k16 = ((lane >> 3) & 1) << 4;
    uint32_t rowA[2], rowB[4];
    #pragma unroll
    for (int mt = 0; mt < 2; mt++)
        rowA[mt] = (uint32_t)(warp_i * 32 + mt * 16 + ((aq & 1) << 3) + (lane & 7)) * 128;
    #pragma unroll
    for (int g = 0; g < 4; g++)
        rowB[g] = (uint32_t)(warp_j * 64 + g * 16 + (((lane >> 4) & 1) << 3) + (lane & 7)) * 128;

    float acc[2][8][4];
    #pragma unroll
    for (int mt = 0; mt < 2; mt++)
        #pragma unroll
        for (int nt = 0; nt < 8; nt++)
            #pragma unroll
            for (int e = 0; e < 4; e++) acc[mt][nt][e] = 0.0f;
    float rowmin[4], rowcex[4];
    #pragma unroll
    for (int i = 0; i < 4; i++) { rowmin[i] = INF; rowcex[i] = INF; }

    auto flush = [&](int nt) {
        __syncthreads();
        float* redM = (float*)smem;             // reuse A region: [128][8] x2
        float* redC = redM + 128 * 8;
        const int slot = warp_j * 4 + (lane & 3);
        #pragma unroll
        for (int i = 0; i < 4; i++) {
            int nl = warp_i * 32 + (i >> 1) * 16 + (i & 1) * 8 + (lane >> 2);
            redM[nl * 8 + slot] = rowmin[i];
            redC[nl * 8 + slot] = rowcex[i];
            rowmin[i] = INF; rowcex[i] = INF;
        }
        __syncthreads();
        if (tid < 128) {
            float m = INF, c = INF;
            #pragma unroll
            for (int k = 0; k < 8; k++) {
                m = fminf(m, redM[tid * 8 + k]);
                c = fminf(c, redC[tid * 8 + k]);
            }
            if (m < INF) atomicMinF(&g_minM[nt * 128 + tid], m);
            if (c < INF) atomicMinF(&g_cex [nt * 128 + tid], c);
        }
        __syncthreads();
    };

    load_A(cur_nt);
    issue_chunk(c0);
    if (c0 + 1 < c1) issue_chunk(c0 + 1);

    #pragma unroll 1
    for (int ci = c0; ci < c1; ci++) {
        if ((ci & 3) == 0) {
            int nt = ci >> 8;                    // (ci/4)/64
            if (nt != cur_nt) {
                flush(cur_nt);
                load_A(nt);                      // drains pending B copies (ok)
                cur_nt = nt;
            }
        }
        CP_WAIT(1);                              // chunk ci arrived
        __syncthreads();                         // all warps done reading ci-1
        if (ci + 2 < c1) issue_chunk(ci + 2);    // stage (ci+2)%3: safe post-sync

        const int s = ci % NSTAGE, kc = ci & 3;
        const uint32_t aHi = sb + SM_A + kc * 16384;
        const uint32_t bHi = sb + SM_B + s * 16384;

        // ks-phase rotation: warps start at different k-offsets so their
        // LDSM bursts hit different smem columns and de-phase vs MMA bursts.
        #pragma unroll
        for (int kk = 0; kk < 4; kk++) {
            const int ks = (kk + warp_i) & 3;
            const uint32_t kbA = ((uint32_t)(ks * 32) + a_k16) ^ xor7;
            const uint32_t kbB = ((uint32_t)(ks * 32) + b_k16) ^ xor7;
            uint32_t Ah[2][4];
            #pragma unroll
            for (int mt = 0; mt < 2; mt++)
                ldsm_x4(Ah[mt], aHi + rowA[mt] + kbA);
            #pragma unroll
            for (int g = 0; g < 4; g++) {
                uint32_t r[4];
                ldsm_x4(r, bHi + rowB[g] + kbB);
                uint32_t b0[2] = {r[0], r[1]}, b1[2] = {r[2], r[3]};
                mma16816(acc[0][2*g],   Ah[0], b0);
                mma16816(acc[0][2*g+1], Ah[0], b1);
                mma16816(acc[1][2*g],   Ah[1], b0);
                mma16816(acc[1][2*g+1], Ah[1], b1);
            }
        }

        if ((ci & 3) == 3) {   // m-tile complete: fold into running row-mins
            #pragma unroll
            for (int mt = 0; mt < 2; mt++)
                #pragma unroll
                for (int nt = 0; nt < 8; nt++)
                    #pragma unroll
                    for (int e = 0; e < 4; e++) {
                        float M = acc[mt][nt][e];
                        acc[mt][nt][e] = 0.0f;
                        int ri = mt * 2 + (e >> 1);
                        if (M > 0.5f) {      // cold exact path (monotonicity edge)
                            float z = (M - 1.0f) * INVS;
                            float lp = fmaf(-0.5f * z, z, LOGC);
                            rowcex[ri] = fminf(rowcex[ri], -expf(lp) * lp);
                        } else {
                            rowmin[ri] = fminf(rowmin[ri], M);
                        }
                    }
        }
    }
    flush(cur_nt);
}

// ---------------- final combine (parallel, separate launch) ----------------
__global__ void __launch_bounds__(256) combine_kernel(float* __restrict__ out) {
    int n = blockIdx.x * 256 + threadIdx.x;
    float m  = g_minM[n];
    float ce = g_cex[n];
    float C = __int_as_float(0x7f800000);
    if (m < 2.0f) {
        float z = (m - 1.0f) * INVS;
        float lp = fmaf(-0.5f * z, z, LOGC);
        C = -expf(lp) * lp;
    }
    out[n] = fminf(C, ce);
}

// ---------------------------------------------------------------------------
extern "C" void kernel_launch(void* const* d_in, const int* in_sizes, int n_in,
                              void* d_out, int out_size) {
    const float* Ex = (const float*)d_in[0];
    const float* Ey = (const float*)d_in[1];
    float* out = (float*)d_out;

    dim3 ngrid(NROWS / 16, 2);
    norm_kernel<<<ngrid, 256>>>(Ex, Ey);

    cudaFuncSetAttribute(gemm_min_kernel,
                         cudaFuncAttributeMaxDynamicSharedMemorySize, SMEM_TOTAL);
    gemm_min_kernel<<<GRID, 256, SMEM_TOTAL>>>();

    combine_kernel<<<NROWS / 256, 256>>>(out);
}